// round 14
// baseline (speedup 1.0000x reference)
#include <cuda_runtime.h>
#include <cuda_fp16.h>
#include <cstdint>

// DeconvCapsuleLayer, round 14: split into two kernels.
//   Kernel A (votes): round-13 GEMM skeleton (single-term fp16 mma.sync,
//     M=64 tiles, 3 blocks/SM) but instead of routing, spills the half2 D
//     tile verbatim (swizzled) to a __device__ staging buffer, coalesced.
//   Kernel B (routing): one warp per output pixel, NO barriers, NO smem,
//     high occupancy hides the shuffle/MUFU chains.
// Numerics identical to round 13 (votes already passed through half2 there).
//
// Reference quirk reproduced: route i of output batch b uses input
// (bb, cin) = ((8b+i)&3, (8b+i)>>2).

namespace {
constexpr int HIN = 56, WIN = 56, CIN = 8, AIN = 32;
constexpr int HP = 112, WP = 112;
constexpr int XN = 4 * 56 * 56 * 8 * 32;     // elements in x
constexpr int BN = 4 * 128 * 128;            // elements in B (hi only)
constexpr int TPC = 1568;                    // tiles per class (8 pixels each)
// Kernel A SMEM: B 32KB | A 16KB | D 16KB (half2, 64 rows x 256B, swizzled)
constexpr int SM_B = 0;
constexpr int SM_A = 32768;
constexpr int SM_D = 49152;
constexpr int SMEM_TOTAL = 65536;
constexpr int NBLK = 111;                    // blocks per class (444 = 148*3)
}

// Pre-swizzled B_hi: [cls(4)][n(128)][k(128)] fp16.
__device__ __half g_B[BN];
// fp16 hi of x
__device__ __half g_xh[XN];
// Staged votes: [cls(4)][tile(1568)][row(64)][col(128)] half, rows swizzled
// with off(r, cb) = r*256 + (cb ^ ((r&7)<<4)). ~98MB.
__device__ __half g_D[(size_t)4 * TPC * 64 * 128];

__global__ void prep_kernel(const float* __restrict__ W,
                            const float* __restrict__ x) {
    int idx = blockIdx.x * blockDim.x + threadIdx.x;
    if (idx < BN) {
        int k   = idx & 127;
        int n   = (idx >> 7) & 127;
        int cls = idx >> 14;
        int t = k >> 5, ain = k & 31;
        int hpar = cls >> 1, wpar = cls & 1;
        int p = (1 - hpar) + 2 * (t >> 1);
        int q = (1 - wpar) + 2 * (t & 1);
        float wv = W[((p * 4 + q) * 128 + n) * AIN + ain];
        uint32_t off = (uint32_t)(n * 256)
                     + (((uint32_t)(k * 2)) ^ ((uint32_t)(n & 7) << 4));
        *(__half*)((char*)g_B + (((size_t)cls) << 15) + off) = __float2half_rn(wv);
    }
    if (idx < XN) {
        g_xh[idx] = __float2half_rn(x[idx]);
    }
}

// ---------------- PTX helpers ----------------
__device__ __forceinline__ void cpa16(uint32_t dst, const void* src, uint32_t srcsize) {
    asm volatile("cp.async.cg.shared.global [%0], [%1], 16, %2;"
                 :: "r"(dst), "l"(src), "r"(srcsize) : "memory");
}
__device__ __forceinline__ void cpa_commit() {
    asm volatile("cp.async.commit_group;" ::: "memory");
}
__device__ __forceinline__ void ldm_x4(uint32_t* r, uint32_t addr) {
    asm volatile("ldmatrix.sync.aligned.m8n8.x4.shared.b16 {%0,%1,%2,%3}, [%4];"
                 : "=r"(r[0]), "=r"(r[1]), "=r"(r[2]), "=r"(r[3]) : "r"(addr));
}
__device__ __forceinline__ void mma_f16(float* d, const uint32_t* a, const uint32_t* b) {
    asm volatile("mma.sync.aligned.m16n8k16.row.col.f32.f16.f16.f32 "
                 "{%0,%1,%2,%3}, {%4,%5,%6,%7}, {%8,%9}, {%0,%1,%2,%3};"
                 : "+f"(d[0]), "+f"(d[1]), "+f"(d[2]), "+f"(d[3])
                 : "r"(a[0]), "r"(a[1]), "r"(a[2]), "r"(a[3]), "r"(b[0]), "r"(b[1]));
}
__device__ __forceinline__ uint32_t pack_h2(float a, float b) {
    __half2 h = __floats2half2_rn(a, b);
    return *(uint32_t*)&h;
}

// ==================== Kernel A: votes GEMM ====================
__global__ void __launch_bounds__(256, 3)
votes_kernel()
{
    extern __shared__ char smem[];
    const uint32_t sbase = (uint32_t)__cvta_generic_to_shared(smem);
    const int tid  = threadIdx.x;
    const int lane = tid & 31;
    const int wid  = tid >> 5;
    const int cls  = blockIdx.y;
    const int blk  = blockIdx.x;
    const int hpar = cls >> 1, wpar = cls & 1;

    // 1568 tiles over 111 blocks -> first 14 get 15, rest 14
    const int base = blk * 14 + (blk < 14 ? blk : 14);
    const int cnt  = 14 + (blk < 14 ? 1 : 0);

    // ---- B copy (pre-swizzled, 32KB) via cp.async
    {
        const char* Bsrc = (const char*)g_B + ((size_t)cls << 15);
        #pragma unroll
        for (int i = 0; i < 8; ++i) {
            uint32_t o = (uint32_t)(tid + 256 * i) * 16;
            cpa16(sbase + SM_B + o, Bsrc + o, 16);
        }
        cpa_commit();
    }

    // ---- gather constants: row m = tid>>2 (0..63), tap = tid&3
    const int m = tid >> 2, mytap = tid & 3;
    const int mypix = m >> 3, route = m & 7;
    const uint32_t rx_m = (uint32_t)(m & 7) << 4;

    auto gather = [&](int T) {
        const int P   = T * 8 + mypix;
        const int b   = P / 3136;
        const int rem = P - b * 3136;
        const int hh  = rem / 56, ww = rem - (rem / 56) * 56;
        const int h   = hpar + 2 * hh;
        const int w   = wpar + 2 * ww;
        const int ih  = (h + 1) >> 1, jw = (w + 1) >> 1;
        const int nn  = b * 8 + route;         // reference reshape quirk
        const int bb  = nn & 3, cin = nn >> 2;
        const int ii = ih - (mytap >> 1);
        const int jj = jw - (mytap & 1);
        const bool valid = ((unsigned)ii < (unsigned)HIN) && ((unsigned)jj < (unsigned)WIN);
        const int iic = valid ? ii : 0, jjc = valid ? jj : 0;
        const uint32_t ssz = valid ? 16u : 0u;
        const char* shi = (const char*)(g_xh
            + (size_t)(((bb * HIN + iic) * WIN + jjc) * CIN + cin) * AIN);
        #pragma unroll
        for (int c = 0; c < 4; ++c) {
            const uint32_t cb  = (uint32_t)(mytap * 4 + c);
            const uint32_t dof = (uint32_t)m * 256 + ((cb << 4) ^ rx_m);
            cpa16(sbase + SM_A + dof, shi + c * 16, ssz);
        }
        cpa_commit();
    };

    // ---- mainloop constants
    const int mb    = (wid & 1) * 32;
    const int nbase = (wid >> 1) * 32;
    const int ar = lane & 15;
    const uint32_t rowA0 = (uint32_t)((mb + ar) * 256);
    const uint32_t rowA1 = (uint32_t)((mb + 16 + ar) * 256);
    const uint32_t a_kl  = (uint32_t)((lane >> 4) << 4);
    const uint32_t rxA   = (uint32_t)(ar & 7) << 4;
    const int brr = (lane & 7) + ((lane >> 4) << 3);
    uint32_t rowB[2];
    #pragma unroll
    for (int nt = 0; nt < 2; ++nt)
        rowB[nt] = (uint32_t)((nbase + nt * 16 + brr) * 256);
    const uint32_t b_kl = (uint32_t)(((lane >> 3) & 1) << 4);
    const uint32_t rxB  = (uint32_t)(lane & 7) << 4;

    // D-staging constants
    const int dg  = lane >> 2;
    const int dc2 = (lane & 3) * 2;
    const uint32_t dxor = (uint32_t)dg << 4;

    gather(base);

    #pragma unroll 1
    for (int it = 0; it < cnt; ++it) {
        asm volatile("cp.async.wait_group 0;" ::: "memory");
        __syncthreads();   // A(t) (and B on t=0) visible

        float d[2][4][4];
        #pragma unroll
        for (int mi = 0; mi < 2; ++mi)
            #pragma unroll
            for (int nq = 0; nq < 4; ++nq)
                #pragma unroll
                for (int j = 0; j < 4; ++j) d[mi][nq][j] = 0.f;

        {
            const uint32_t Ahi = sbase + SM_A;
            const uint32_t Bhi = sbase + SM_B;
            #pragma unroll
            for (int k0 = 0; k0 < 128; k0 += 16) {
                const uint32_t ka = ((uint32_t)(k0 * 2) + a_kl) ^ rxA;
                const uint32_t kb = ((uint32_t)(k0 * 2) + b_kl) ^ rxB;
                uint32_t ahi[2][4], bfr[4];
                ldm_x4(ahi[0], Ahi + rowA0 + ka);
                ldm_x4(ahi[1], Ahi + rowA1 + ka);
                #pragma unroll
                for (int nt = 0; nt < 2; ++nt) {
                    ldm_x4(bfr, Bhi + rowB[nt] + kb);
                    #pragma unroll
                    for (int mi = 0; mi < 2; ++mi) {
                        mma_f16(d[mi][nt * 2 + 0], ahi[mi], bfr + 0);
                        mma_f16(d[mi][nt * 2 + 1], ahi[mi], bfr + 2);
                    }
                }
            }
        }

        // ---- stage D as half2 into disjoint D region (swizzled)
        {
            char* Dp = smem + SM_D;
            #pragma unroll
            for (int mi = 0; mi < 2; ++mi) {
                #pragma unroll
                for (int nq = 0; nq < 4; ++nq) {
                    const int col = nbase + nq * 8 + dc2;
                    const int r0  = mb + mi * 16 + dg;
                    const uint32_t cbs = ((uint32_t)(col * 2)) ^ dxor;
                    *(uint32_t*)(Dp + (uint32_t)r0 * 256 + cbs)
                        = pack_h2(d[mi][nq][0], d[mi][nq][1]);
                    *(uint32_t*)(Dp + (uint32_t)(r0 + 8) * 256 + cbs)
                        = pack_h2(d[mi][nq][2], d[mi][nq][3]);
                }
            }
        }
        __syncthreads();   // D visible; all A reads done

        // ---- hoisted gather for t+1 (writes A only)
        if (it + 1 < cnt) gather(base + it + 1);

        // ---- spill D tile verbatim (still swizzled) to global, coalesced
        {
            const char* Dp = smem + SM_D;
            char* dst = (char*)g_D
                      + ((size_t)(cls * TPC + (base + it)) << 14);  // *16384
            #pragma unroll
            for (int j = 0; j < 4; ++j) {
                uint32_t o = (uint32_t)(tid + 256 * j) * 16;
                uint4 v = *(const uint4*)(Dp + o);
                *(uint4*)(dst + o) = v;
            }
        }
    }
}

// ==================== Kernel B: routing ====================
__global__ void __launch_bounds__(256)
routing_kernel(const float* __restrict__ bias,
               float* __restrict__ out)
{
    const int lane = threadIdx.x & 31;
    const int wid  = threadIdx.x >> 5;     // pixel within tile (0..7)
    const int T    = blockIdx.x;
    const int cls  = blockIdx.y;
    const int hpar = cls >> 1, wpar = cls & 1;

    // ---- load acc: rows wid*8..wid*8+7 of the staged (swizzled) D tile
    const char* Dg = (const char*)g_D + ((size_t)(cls * TPC + T) << 14);
    float acc[8][4];
    #pragma unroll
    for (int i = 0; i < 8; ++i) {
        const int R = wid * 8 + i;                 // R&7 == i
        const char* p = Dg + (uint32_t)R * 256
                      + (((uint32_t)(lane * 8)) ^ ((uint32_t)i << 4));
        uint2 v = __ldg((const uint2*)p);
        float2 f0 = __half22float2(*(__half2*)&v.x);
        float2 f1 = __half22float2(*(__half2*)&v.y);
        acc[i][0] = f0.x; acc[i][1] = f0.y;
        acc[i][2] = f1.x; acc[i][3] = f1.y;
    }

    const float4 bs = __ldg((const float4*)bias + lane);

    float logits[8];
    float a0, a1, a2, a3;

    // iteration 0: softmax(0) == 0.125 exactly
    {
        float p0 = bs.x, p1 = bs.y, p2 = bs.z, p3 = bs.w;
        float s0 = 0.f, s1 = 0.f, s2 = 0.f, s3 = 0.f;
        #pragma unroll
        for (int i = 0; i < 8; ++i) {
            s0 += acc[i][0]; s1 += acc[i][1];
            s2 += acc[i][2]; s3 += acc[i][3];
        }
        p0 = fmaf(0.125f, s0, p0); p1 = fmaf(0.125f, s1, p1);
        p2 = fmaf(0.125f, s2, p2); p3 = fmaf(0.125f, s3, p3);
        float sq = p0 * p0 + p1 * p1 + p2 * p2 + p3 * p3;
        sq += __shfl_xor_sync(0xffffffffu, sq, 1);
        sq += __shfl_xor_sync(0xffffffffu, sq, 2);
        float scale = __fdividef(sq, 1.0f + sq) * rsqrtf(sq + 1e-9f);
        a0 = p0 * scale; a1 = p1 * scale; a2 = p2 * scale; a3 = p3 * scale;
        #pragma unroll
        for (int i = 0; i < 8; ++i) {
            float dd = acc[i][0] * a0 + acc[i][1] * a1
                     + acc[i][2] * a2 + acc[i][3] * a3;
            dd += __shfl_xor_sync(0xffffffffu, dd, 1);
            dd += __shfl_xor_sync(0xffffffffu, dd, 2);
            logits[i] = dd;
        }
    }

    // iterations 1,2: softmax without max-sub (|logits| small)
    #pragma unroll
    for (int itr = 1; itr < 3; ++itr) {
        float r[8];
        #pragma unroll
        for (int i = 0; i < 8; ++i) {
            float e = __expf(logits[i]);
            float ss = e;
            ss += __shfl_xor_sync(0xffffffffu, ss, 4);
            ss += __shfl_xor_sync(0xffffffffu, ss, 8);
            ss += __shfl_xor_sync(0xffffffffu, ss, 16);
            r[i] = __fdividef(e, ss);
        }
        float p0 = bs.x, p1 = bs.y, p2 = bs.z, p3 = bs.w;
        #pragma unroll
        for (int i = 0; i < 8; ++i) {
            p0 = fmaf(r[i], acc[i][0], p0);
            p1 = fmaf(r[i], acc[i][1], p1);
            p2 = fmaf(r[i], acc[i][2], p2);
            p3 = fmaf(r[i], acc[i][3], p3);
        }
        float sq = p0 * p0 + p1 * p1 + p2 * p2 + p3 * p3;
        sq += __shfl_xor_sync(0xffffffffu, sq, 1);
        sq += __shfl_xor_sync(0xffffffffu, sq, 2);
        float scale = __fdividef(sq, 1.0f + sq) * rsqrtf(sq + 1e-9f);
        a0 = p0 * scale; a1 = p1 * scale; a2 = p2 * scale; a3 = p3 * scale;

        if (itr == 1) {
            #pragma unroll
            for (int i = 0; i < 8; ++i) {
                float dd = acc[i][0] * a0 + acc[i][1] * a1
                         + acc[i][2] * a2 + acc[i][3] * a3;
                dd += __shfl_xor_sync(0xffffffffu, dd, 1);
                dd += __shfl_xor_sync(0xffffffffu, dd, 2);
                logits[i] += dd;
            }
        }
    }

    const int P   = T * 8 + wid;
    const int b   = P / 3136;
    const int rem = P - b * 3136;
    const int hh  = rem / 56, ww = rem - (rem / 56) * 56;
    const int h   = hpar + 2 * hh;
    const int w   = wpar + 2 * ww;
    ((float4*)out)[(size_t)((b * HP + h) * WP + w) * 32 + lane]
        = make_float4(a0, a1, a2, a3);
}

extern "C" void kernel_launch(void* const* d_in, const int* in_sizes, int n_in,
                              void* d_out, int out_size) {
    const float* x = nullptr;
    const float* W = nullptr;
    const float* bias = nullptr;
    for (int i = 0; i < n_in; ++i) {
        if (in_sizes[i] == XN)                    x    = (const float*)d_in[i];
        else if (in_sizes[i] == 4 * 4 * 128 * 32) W    = (const float*)d_in[i];
        else if (in_sizes[i] == 128)              bias = (const float*)d_in[i];
    }
    float* out = (float*)d_out;

    cudaFuncSetAttribute(votes_kernel,
                         cudaFuncAttributeMaxDynamicSharedMemorySize, SMEM_TOTAL);

    prep_kernel<<<(XN + 255) / 256, 256>>>(W, x);

    dim3 gridA(NBLK, 4);
    votes_kernel<<<gridA, 256, SMEM_TOTAL>>>();

    dim3 gridB(TPC, 4);
    routing_kernel<<<gridB, 256>>>(bias, out);
}

// round 15
// speedup vs baseline: 1.1446x; 1.1446x over previous
#include <cuda_runtime.h>
#include <cuda_fp16.h>
#include <cstdint>

// DeconvCapsuleLayer, round 15: round-13 fused kernel (best: 99.8us) with a
// vectorized prep kernel (round 14's split regressed: kernels serialize, and
// ncu showed prep itself costing ~12us at one elem/thread).
//   prep: x converted 8 elems/thread (2x float4 -> uint4 of halves, coalesced);
//         B prep folded into the first 64K threads.
//   main: single-term fp16 mma.sync GEMM, M=64 tiles, 3 blocks/SM, D staged
//         as half2 disjoint from A (2 syncs/tile), register routing.
//
// Reference quirk reproduced: route i of output batch b uses input
// (bb, cin) = ((8b+i)&3, (8b+i)>>2).

namespace {
constexpr int HIN = 56, WIN = 56, CIN = 8, AIN = 32;
constexpr int HP = 112, WP = 112;
constexpr int XN = 4 * 56 * 56 * 8 * 32;     // elements in x
constexpr int BN = 4 * 128 * 128;            // elements in B (hi only)
// SMEM map: B 32KB | A 16KB | D 16KB (half2, 64 rows x 256B)
constexpr int SM_B = 0;
constexpr int SM_A = 32768;
constexpr int SM_D = 49152;
constexpr int SMEM_TOTAL = 65536;
constexpr int NBLK = 111;                    // blocks per class (444 = 148*3)
}

// Pre-swizzled B_hi: [cls(4)][n(128)][k(128)] fp16.
__device__ __half g_B[BN];
// fp16 hi of x: [bb][ii][jj][cin][ain]
__device__ __half g_xh[XN];

__global__ void __launch_bounds__(256)
prep_kernel(const float* __restrict__ W, const float* __restrict__ x) {
    int idx = blockIdx.x * blockDim.x + threadIdx.x;

    // ---- x: 8 elements per thread, coalesced float4 loads -> uint4 store
    if (idx < XN / 8) {
        const float4* xs = (const float4*)x + idx * 2;
        float4 v0 = xs[0];
        float4 v1 = xs[1];
        __half2 h0 = __floats2half2_rn(v0.x, v0.y);
        __half2 h1 = __floats2half2_rn(v0.z, v0.w);
        __half2 h2 = __floats2half2_rn(v1.x, v1.y);
        __half2 h3 = __floats2half2_rn(v1.z, v1.w);
        uint4 pk = make_uint4(*(uint32_t*)&h0, *(uint32_t*)&h1,
                              *(uint32_t*)&h2, *(uint32_t*)&h3);
        ((uint4*)g_xh)[idx] = pk;
    }

    // ---- B: one element per thread (small: 64K)
    if (idx < BN) {
        int k   = idx & 127;
        int n   = (idx >> 7) & 127;
        int cls = idx >> 14;
        int t = k >> 5, ain = k & 31;
        int hpar = cls >> 1, wpar = cls & 1;
        int p = (1 - hpar) + 2 * (t >> 1);
        int q = (1 - wpar) + 2 * (t & 1);
        float wv = W[((p * 4 + q) * 128 + n) * AIN + ain];
        uint32_t off = (uint32_t)(n * 256)
                     + (((uint32_t)(k * 2)) ^ ((uint32_t)(n & 7) << 4));
        *(__half*)((char*)g_B + (((size_t)cls) << 15) + off) = __float2half_rn(wv);
    }
}

// ---------------- PTX helpers ----------------
__device__ __forceinline__ void cpa16(uint32_t dst, const void* src, uint32_t srcsize) {
    asm volatile("cp.async.cg.shared.global [%0], [%1], 16, %2;"
                 :: "r"(dst), "l"(src), "r"(srcsize) : "memory");
}
__device__ __forceinline__ void cpa_commit() {
    asm volatile("cp.async.commit_group;" ::: "memory");
}
__device__ __forceinline__ void ldm_x4(uint32_t* r, uint32_t addr) {
    asm volatile("ldmatrix.sync.aligned.m8n8.x4.shared.b16 {%0,%1,%2,%3}, [%4];"
                 : "=r"(r[0]), "=r"(r[1]), "=r"(r[2]), "=r"(r[3]) : "r"(addr));
}
__device__ __forceinline__ void mma_f16(float* d, const uint32_t* a, const uint32_t* b) {
    asm volatile("mma.sync.aligned.m16n8k16.row.col.f32.f16.f16.f32 "
                 "{%0,%1,%2,%3}, {%4,%5,%6,%7}, {%8,%9}, {%0,%1,%2,%3};"
                 : "+f"(d[0]), "+f"(d[1]), "+f"(d[2]), "+f"(d[3])
                 : "r"(a[0]), "r"(a[1]), "r"(a[2]), "r"(a[3]), "r"(b[0]), "r"(b[1]));
}
__device__ __forceinline__ uint32_t pack_h2(float a, float b) {
    __half2 h = __floats2half2_rn(a, b);
    return *(uint32_t*)&h;
}

__global__ void __launch_bounds__(256, 3)
deconv_caps_pers_kernel(const float* __restrict__ bias,
                        float* __restrict__ out)
{
    extern __shared__ char smem[];
    const uint32_t sbase = (uint32_t)__cvta_generic_to_shared(smem);
    const int tid  = threadIdx.x;
    const int lane = tid & 31;
    const int wid  = tid >> 5;
    const int cls  = blockIdx.y;
    const int blk  = blockIdx.x;
    const int hpar = cls >> 1, wpar = cls & 1;

    // tile range: 1568 tiles over 111 blocks -> first 14 get 15, rest 14
    const int base = blk * 14 + (blk < 14 ? blk : 14);
    const int cnt  = 14 + (blk < 14 ? 1 : 0);

    // ---- issue B copy (pre-swizzled, 32KB) via cp.async
    {
        const char* Bsrc = (const char*)g_B + ((size_t)cls << 15);
        #pragma unroll
        for (int i = 0; i < 8; ++i) {
            uint32_t o = (uint32_t)(tid + 256 * i) * 16;
            cpa16(sbase + SM_B + o, Bsrc + o, 16);
        }
        cpa_commit();
    }

    // ---- per-thread gather constants: row m = tid>>2 (0..63), tap = tid&3
    const int m = tid >> 2, mytap = tid & 3;
    const int mypix = m >> 3, route = m & 7;   // pixel 0..7 within tile
    const uint32_t rx_m = (uint32_t)(m & 7) << 4;

    auto gather = [&](int T) {
        const int P   = T * 8 + mypix;
        const int b   = P / 3136;
        const int rem = P - b * 3136;
        const int hh  = rem / 56, ww = rem - (rem / 56) * 56;
        const int h   = hpar + 2 * hh;
        const int w   = wpar + 2 * ww;
        const int ih  = (h + 1) >> 1, jw = (w + 1) >> 1;
        const int nn  = b * 8 + route;         // reference reshape quirk
        const int bb  = nn & 3, cin = nn >> 2;
        const int ii = ih - (mytap >> 1);
        const int jj = jw - (mytap & 1);
        const bool valid = ((unsigned)ii < (unsigned)HIN) && ((unsigned)jj < (unsigned)WIN);
        const int iic = valid ? ii : 0, jjc = valid ? jj : 0;
        const uint32_t ssz = valid ? 16u : 0u;
        const char* shi = (const char*)(g_xh
            + (size_t)(((bb * HIN + iic) * WIN + jjc) * CIN + cin) * AIN);
        #pragma unroll
        for (int c = 0; c < 4; ++c) {
            const uint32_t cb  = (uint32_t)(mytap * 4 + c);
            const uint32_t dof = (uint32_t)m * 256 + ((cb << 4) ^ rx_m);
            cpa16(sbase + SM_A + dof, shi + c * 16, ssz);
        }
        cpa_commit();
    };

    // ---- mainloop constants: warp tile rows mb..mb+31 (of 64), cols nbase..+31
    const int mb    = (wid & 1) * 32;
    const int nbase = (wid >> 1) * 32;
    const int ar = lane & 15;
    const uint32_t rowA0 = (uint32_t)((mb + ar) * 256);
    const uint32_t rowA1 = (uint32_t)((mb + 16 + ar) * 256);
    const uint32_t a_kl  = (uint32_t)((lane >> 4) << 4);
    const uint32_t rxA   = (uint32_t)(ar & 7) << 4;
    const int brr = (lane & 7) + ((lane >> 4) << 3);
    uint32_t rowB[2];
    #pragma unroll
    for (int nt = 0; nt < 2; ++nt)
        rowB[nt] = (uint32_t)((nbase + nt * 16 + brr) * 256);
    const uint32_t b_kl = (uint32_t)(((lane >> 3) & 1) << 4);
    const uint32_t rxB  = (uint32_t)(lane & 7) << 4;

    // D-staging constants (store side)
    const int dg  = lane >> 2;
    const int dc2 = (lane & 3) * 2;
    const uint32_t dxor = (uint32_t)dg << 4;

    const float4 bs = __ldg((const float4*)bias + lane);

    // prologue gather of tile 0
    gather(base);

    #pragma unroll 1
    for (int it = 0; it < cnt; ++it) {
        asm volatile("cp.async.wait_group 0;" ::: "memory");
        __syncthreads();   // sync #1: A(t) (and B on t=0) visible to all warps

        // ---- mainloop: 8 k-steps, single fp16 term
        float d[2][4][4];
        #pragma unroll
        for (int mi = 0; mi < 2; ++mi)
            #pragma unroll
            for (int nq = 0; nq < 4; ++nq)
                #pragma unroll
                for (int j = 0; j < 4; ++j) d[mi][nq][j] = 0.f;

        {
            const uint32_t Ahi = sbase + SM_A;
            const uint32_t Bhi = sbase + SM_B;
            #pragma unroll
            for (int k0 = 0; k0 < 128; k0 += 16) {
                const uint32_t ka = ((uint32_t)(k0 * 2) + a_kl) ^ rxA;
                const uint32_t kb = ((uint32_t)(k0 * 2) + b_kl) ^ rxB;
                uint32_t ahi[2][4], bfr[4];
                ldm_x4(ahi[0], Ahi + rowA0 + ka);
                ldm_x4(ahi[1], Ahi + rowA1 + ka);
                #pragma unroll
                for (int nt = 0; nt < 2; ++nt) {
                    ldm_x4(bfr, Bhi + rowB[nt] + kb);
                    #pragma unroll
                    for (int mi = 0; mi < 2; ++mi) {
                        mma_f16(d[mi][nt * 2 + 0], ahi[mi], bfr + 0);
                        mma_f16(d[mi][nt * 2 + 1], ahi[mi], bfr + 2);
                    }
                }
            }
        }

        // ---- stage D as half2 into disjoint D region
        {
            char* Dp = smem + SM_D;
            #pragma unroll
            for (int mi = 0; mi < 2; ++mi) {
                #pragma unroll
                for (int nq = 0; nq < 4; ++nq) {
                    const int col = nbase + nq * 8 + dc2;
                    const int r0  = mb + mi * 16 + dg;
                    const uint32_t cbs = ((uint32_t)(col * 2)) ^ dxor;
                    *(uint32_t*)(Dp + (uint32_t)r0 * 256 + cbs)
                        = pack_h2(d[mi][nq][0], d[mi][nq][1]);
                    *(uint32_t*)(Dp + (uint32_t)(r0 + 8) * 256 + cbs)
                        = pack_h2(d[mi][nq][2], d[mi][nq][3]);
                }
            }
        }
        __syncthreads();   // sync #2: all D visible (also: all A reads done)

        // ---- load routing acc regs (one pixel per warp) from half2 D
        float acc[8][4];
        {
            const char* Dp = smem + SM_D;
            #pragma unroll
            for (int i = 0; i < 8; ++i) {
                const int R = wid * 8 + i;
                uint32_t off = (uint32_t)R * 256
                             + (((uint32_t)(lane * 8)) ^ ((uint32_t)i << 4));
                uint2 v = *(const uint2*)(Dp + off);
                float2 f0 = __half22float2(*(__half2*)&v.x);
                float2 f1 = __half22float2(*(__half2*)&v.y);
                acc[i][0] = f0.x; acc[i][1] = f0.y;
                acc[i][2] = f1.x; acc[i][3] = f1.y;
            }
        }

        // ---- hoisted gather: writes A only (disjoint from D) -> no sync.
        if (it + 1 < cnt) gather(base + it + 1);

        // ---- routing math (registers + shuffles only)
        {
            float logits[8];
            float a0, a1, a2, a3;

            // iteration 0: softmax(0) == 0.125 exactly
            {
                float p0 = bs.x, p1 = bs.y, p2 = bs.z, p3 = bs.w;
                float s0 = 0.f, s1 = 0.f, s2 = 0.f, s3 = 0.f;
                #pragma unroll
                for (int i = 0; i < 8; ++i) {
                    s0 += acc[i][0]; s1 += acc[i][1];
                    s2 += acc[i][2]; s3 += acc[i][3];
                }
                p0 = fmaf(0.125f, s0, p0); p1 = fmaf(0.125f, s1, p1);
                p2 = fmaf(0.125f, s2, p2); p3 = fmaf(0.125f, s3, p3);
                float sq = p0 * p0 + p1 * p1 + p2 * p2 + p3 * p3;
                sq += __shfl_xor_sync(0xffffffffu, sq, 1);
                sq += __shfl_xor_sync(0xffffffffu, sq, 2);
                float scale = __fdividef(sq, 1.0f + sq) * rsqrtf(sq + 1e-9f);
                a0 = p0 * scale; a1 = p1 * scale; a2 = p2 * scale; a3 = p3 * scale;
                #pragma unroll
                for (int i = 0; i < 8; ++i) {
                    float dd = acc[i][0] * a0 + acc[i][1] * a1
                             + acc[i][2] * a2 + acc[i][3] * a3;
                    dd += __shfl_xor_sync(0xffffffffu, dd, 1);
                    dd += __shfl_xor_sync(0xffffffffu, dd, 2);
                    logits[i] = dd;
                }
            }

            // iterations 1,2: softmax without max-sub (|logits| small)
            #pragma unroll
            for (int itr = 1; itr < 3; ++itr) {
                float r[8];
                #pragma unroll
                for (int i = 0; i < 8; ++i) {
                    float e = __expf(logits[i]);
                    float ss = e;
                    ss += __shfl_xor_sync(0xffffffffu, ss, 4);
                    ss += __shfl_xor_sync(0xffffffffu, ss, 8);
                    ss += __shfl_xor_sync(0xffffffffu, ss, 16);
                    r[i] = __fdividef(e, ss);
                }
                float p0 = bs.x, p1 = bs.y, p2 = bs.z, p3 = bs.w;
                #pragma unroll
                for (int i = 0; i < 8; ++i) {
                    p0 = fmaf(r[i], acc[i][0], p0);
                    p1 = fmaf(r[i], acc[i][1], p1);
                    p2 = fmaf(r[i], acc[i][2], p2);
                    p3 = fmaf(r[i], acc[i][3], p3);
                }
                float sq = p0 * p0 + p1 * p1 + p2 * p2 + p3 * p3;
                sq += __shfl_xor_sync(0xffffffffu, sq, 1);
                sq += __shfl_xor_sync(0xffffffffu, sq, 2);
                float scale = __fdividef(sq, 1.0f + sq) * rsqrtf(sq + 1e-9f);
                a0 = p0 * scale; a1 = p1 * scale; a2 = p2 * scale; a3 = p3 * scale;

                if (itr == 1) {
                    #pragma unroll
                    for (int i = 0; i < 8; ++i) {
                        float dd = acc[i][0] * a0 + acc[i][1] * a1
                                 + acc[i][2] * a2 + acc[i][3] * a3;
                        dd += __shfl_xor_sync(0xffffffffu, dd, 1);
                        dd += __shfl_xor_sync(0xffffffffu, dd, 2);
                        logits[i] += dd;
                    }
                }
            }

            const int P   = (base + it) * 8 + wid;
            const int b   = P / 3136;
            const int rem = P - b * 3136;
            const int hh  = rem / 56, ww = rem - (rem / 56) * 56;
            const int h   = hpar + 2 * hh;
            const int w   = wpar + 2 * ww;
            ((float4*)out)[(size_t)((b * HP + h) * WP + w) * 32 + lane]
                = make_float4(a0, a1, a2, a3);
        }
    }
}

extern "C" void kernel_launch(void* const* d_in, const int* in_sizes, int n_in,
                              void* d_out, int out_size) {
    const float* x = nullptr;
    const float* W = nullptr;
    const float* bias = nullptr;
    for (int i = 0; i < n_in; ++i) {
        if (in_sizes[i] == XN)                    x    = (const float*)d_in[i];
        else if (in_sizes[i] == 4 * 4 * 128 * 32) W    = (const float*)d_in[i];
        else if (in_sizes[i] == 128)              bias = (const float*)d_in[i];
    }
    float* out = (float*)d_out;

    cudaFuncSetAttribute(deconv_caps_pers_kernel,
                         cudaFuncAttributeMaxDynamicSharedMemorySize, SMEM_TOTAL);

    // XN/8 = 401408/8... (XN = 3,211,264) -> XN/8 = 401,408 threads
    prep_kernel<<<(XN / 8 + 255) / 256, 256>>>(W, x);

    dim3 grid(NBLK, 4);
    deconv_caps_pers_kernel<<<grid, 256, SMEM_TOTAL>>>(bias, out);
}